// round 15
// baseline (speedup 1.0000x reference)
#include <cuda_runtime.h>
#include <cuda_bf16.h>
#include <math.h>

// Problem constants
namespace {
constexpr int B = 64, T = 256, E = 512, H = 512, TAGS = 50;
constexpr int G = 4 * H;   // 2048 (gate dim)
constexpr int M = T * B;   // 16384 rows
constexpr int NBLK_PER_DIR = 64;
constexpr int GH = G * H;  // 1M elements (one Whh)
}

// Single dynamic shared memory declaration for all kernels.
extern __shared__ char dynsmem[];

// Scratch (static device arrays — no cudaMalloc allowed)
__device__ float g_pre_f[M * G];
__device__ float g_pre_b[M * G];
__device__ float g_out2[M * 2 * H];
__device__ unsigned g_arrive[2][NBLK_PER_DIR];   // flag barrier slots
// bf16 split operands for tensor-core GEMMs
__device__ __align__(256) __nv_bfloat16 g_ahi[M * 1024];
__device__ __align__(256) __nv_bfloat16 g_alo[M * 1024];
__device__ __align__(256) __nv_bfloat16 g_whi[G * 1024];
__device__ __align__(256) __nv_bfloat16 g_wlo[G * 1024];
// recurrent weight splits (both dirs of current layer)
__device__ __align__(256) __nv_bfloat16 g_whhhi[2 * GH];
__device__ __align__(256) __nv_bfloat16 g_whhlo[2 * GH];
// h state in bf16 hi/lo, double buffered: [parity][dir][b*512 + j]
__device__ __align__(256) __nv_bfloat16 g_hbf_hi[2][2][B * H];
__device__ __align__(256) __nv_bfloat16 g_hbf_lo[2][2][B * H];

// ---------------------------------------------------------------------------
__device__ __forceinline__ unsigned s2u32(const void* p) {
  return static_cast<unsigned>(__cvta_generic_to_shared(p));
}
__device__ __forceinline__ void cp_async16(unsigned sa, const void* g) {
  asm volatile("cp.async.cg.shared.global [%0], [%1], 16;" :: "r"(sa), "l"(g));
}
__device__ __forceinline__ void cp_commit() {
  asm volatile("cp.async.commit_group;" ::: "memory");
}
template <int N>
__device__ __forceinline__ void cp_wait() {
  asm volatile("cp.async.wait_group %0;" :: "n"(N) : "memory");
}
__device__ __forceinline__ void ldmx4(unsigned* r, unsigned addr) {
  asm volatile("ldmatrix.sync.aligned.m8n8.x4.shared.b16 {%0,%1,%2,%3}, [%4];"
               : "=r"(r[0]), "=r"(r[1]), "=r"(r[2]), "=r"(r[3]) : "r"(addr));
}
__device__ __forceinline__ void hmma(float* d, const unsigned* a,
                                     unsigned b0, unsigned b1) {
  asm volatile(
      "mma.sync.aligned.m16n8k16.row.col.f32.bf16.bf16.f32 "
      "{%0,%1,%2,%3}, {%4,%5,%6,%7}, {%8,%9}, {%0,%1,%2,%3};"
      : "+f"(d[0]), "+f"(d[1]), "+f"(d[2]), "+f"(d[3])
      : "r"(a[0]), "r"(a[1]), "r"(a[2]), "r"(a[3]), "r"(b0), "r"(b1));
}
__device__ __forceinline__ float sigf(float x) {
  return __fdividef(1.f, 1.f + __expf(-x));
}
__device__ __forceinline__ float tanhf_fast(float x) {
  float e = __expf(2.f * x);
  return 1.f - __fdividef(2.f, e + 1.f);
}

// ---------------------------------------------------------------------------
__global__ void init_layer_kernel() {
  int i = blockIdx.x * blockDim.x + threadIdx.x;
  __nv_bfloat16* hh = &g_hbf_hi[0][0][0];
  __nv_bfloat16* hl = &g_hbf_lo[0][0][0];
  if (i < 2 * 2 * B * H) {
    hh[i] = __float2bfloat16(0.f);
    hl[i] = __float2bfloat16(0.f);
  }
  if (i < 2 * NBLK_PER_DIR) (&g_arrive[0][0])[i] = 0u;
}

// Embedding gather fused with bf16 hi/lo split: writes A operand directly.
__global__ void embed_split_kernel(const int* __restrict__ x,
                                   const float* __restrict__ emb,
                                   __nv_bfloat16* __restrict__ ahi,
                                   __nv_bfloat16* __restrict__ alo) {
  int row = blockIdx.x;
  int t = row >> 6;
  int b = row & 63;
  int tok = x[b * T + t];
  float4 v = reinterpret_cast<const float4*>(emb + (size_t)tok * E)[threadIdx.x];
  __nv_bfloat16 h0 = __float2bfloat16(v.x);
  __nv_bfloat16 h1 = __float2bfloat16(v.y);
  __nv_bfloat16 h2 = __float2bfloat16(v.z);
  __nv_bfloat16 h3 = __float2bfloat16(v.w);
  __nv_bfloat162 hi0; hi0.x = h0; hi0.y = h1;
  __nv_bfloat162 hi1; hi1.x = h2; hi1.y = h3;
  __nv_bfloat162 lo0, lo1;
  lo0.x = __float2bfloat16(v.x - __bfloat162float(h0));
  lo0.y = __float2bfloat16(v.y - __bfloat162float(h1));
  lo1.x = __float2bfloat16(v.z - __bfloat162float(h2));
  lo1.y = __float2bfloat16(v.w - __bfloat162float(h3));
  size_t o = (size_t)row * E + threadIdx.x * 4;
  *reinterpret_cast<__nv_bfloat162*>(ahi + o) = hi0;
  *reinterpret_cast<__nv_bfloat162*>(ahi + o + 2) = hi1;
  *reinterpret_cast<__nv_bfloat162*>(alo + o) = lo0;
  *reinterpret_cast<__nv_bfloat162*>(alo + o + 2) = lo1;
}

// fp32 -> (hi, lo) bf16 split (weights)
__global__ void split_kernel(const float* __restrict__ in,
                             __nv_bfloat16* __restrict__ hi,
                             __nv_bfloat16* __restrict__ lo, int n) {
  int i = blockIdx.x * blockDim.x + threadIdx.x;
  if (i < n) {
    float x = in[i];
    __nv_bfloat16 h = __float2bfloat16(x);
    hi[i] = h;
    lo[i] = __float2bfloat16(x - __bfloat162float(h));
  }
}

// ---------------------------------------------------------------------------
// Split-bf16 HMMA GEMM: 32-k chunks, R15: 4-stage ring (3 chunks in flight).
// C[M,2048] = A[M,K] @ W[2048,K]^T + b1 + b2 over virtual K' = 3K.
template <int K>
__global__ __launch_bounds__(256, 2)
void gemm_split_kernel(const __nv_bfloat16* __restrict__ Ahi,
                       const __nv_bfloat16* __restrict__ Alo,
                       const __nv_bfloat16* __restrict__ Whi,
                       const __nv_bfloat16* __restrict__ Wlo,
                       const float* __restrict__ b1,
                       const float* __restrict__ b2,
                       float* __restrict__ C) {
  constexpr int CPS = K / 32;
  constexpr int NCH = 3 * CPS;
  constexpr int LDS_EL = 40;
  constexpr int TILE_EL = 128 * LDS_EL;            // 5120 el / operand
  constexpr unsigned STAGE_B = 2 * TILE_EL * 2;    // 20480 B per stage
  __nv_bfloat16* smem = reinterpret_cast<__nv_bfloat16*>(dynsmem);
  __shared__ float bias_s[128];

  const int bn = blockIdx.x << 7;
  const int bm = blockIdx.y << 7;
  const int tid = threadIdx.x;
  const int lane = tid & 31;
  const int wid = tid >> 5;
  const int wm = (wid & 3) << 5;
  const int wn = (wid >> 2) << 6;

  if (tid < 128) bias_s[tid] = b1[bn + tid] + b2[bn + tid];

  const unsigned sb = s2u32(smem);
  const __nv_bfloat16* segA[3] = {Ahi, Alo, Ahi};
  const __nv_bfloat16* segW[3] = {Whi, Whi, Wlo};

  const int lrow = tid >> 2;
  const int lc = tid & 3;
  auto load_chunk = [&](int ch) {
    const int s = ch / CPS;
    const int k0 = (ch - s * CPS) << 5;
    const unsigned base = sb + (unsigned)(ch & 3) * STAGE_B;
    const __nv_bfloat16* Ap = segA[s];
    const __nv_bfloat16* Wp = segW[s];
#pragma unroll
    for (int e = 0; e < 2; e++) {
      int r = lrow + (e << 6);
      unsigned so = (unsigned)(r * LDS_EL + lc * 8) * 2;
      cp_async16(base + so, Ap + (size_t)(bm + r) * K + k0 + lc * 8);
      cp_async16(base + TILE_EL * 2 + so,
                 Wp + (size_t)(bn + r) * K + k0 + lc * 8);
    }
    cp_commit();
  };

  load_chunk(0);
  load_chunk(1);
  load_chunk(2);

  float acc[2][8][4];
#pragma unroll
  for (int mi = 0; mi < 2; mi++)
#pragma unroll
    for (int ng = 0; ng < 8; ng++)
#pragma unroll
      for (int q = 0; q < 4; q++) acc[mi][ng][q] = 0.f;

  const int lrow16 = lane & 15;
  const int lcol8 = (lane >> 4) << 3;
  const unsigned aoff0 = (unsigned)((wm + lrow16) * LDS_EL + lcol8) * 2;
  const unsigned aoff1 = (unsigned)((wm + 16 + lrow16) * LDS_EL + lcol8) * 2;
  unsigned woffs[4];
#pragma unroll
  for (int ni = 0; ni < 4; ni++)
    woffs[ni] =
        (unsigned)((wn + ni * 16 + lrow16) * LDS_EL + lcol8) * 2 +
        (unsigned)(TILE_EL * 2);

  for (int ch = 0; ch < NCH; ch++) {
    if (ch + 2 < NCH) cp_wait<2>();
    else if (ch + 1 < NCH) cp_wait<1>();
    else cp_wait<0>();
    __syncthreads();   // buf ch ready AND buf (ch+3)%4's last readers done
    if (ch + 3 < NCH) load_chunk(ch + 3);
    const unsigned base = sb + (unsigned)(ch & 3) * STAGE_B;
#pragma unroll
    for (int kk = 0; kk < 32; kk += 16) {
      unsigned a[2][4], bf[4][4];
      ldmx4(a[0], base + aoff0 + kk * 2);
      ldmx4(a[1], base + aoff1 + kk * 2);
#pragma unroll
      for (int ni = 0; ni < 4; ni++)
        ldmx4(bf[ni], base + woffs[ni] + kk * 2);
#pragma unroll
      for (int mi = 0; mi < 2; mi++)
#pragma unroll
        for (int ng = 0; ng < 8; ng++)
          hmma(acc[mi][ng], a[mi], bf[ng >> 1][ng & 1], bf[ng >> 1][2 + (ng & 1)]);
    }
  }

  const int er = lane >> 2;
  const int ec = (lane & 3) << 1;
#pragma unroll
  for (int mi = 0; mi < 2; mi++) {
    int row0 = bm + wm + mi * 16 + er;
#pragma unroll
    for (int ng = 0; ng < 8; ng++) {
      int col = wn + ng * 8 + ec;
      float2 bv = make_float2(bias_s[col], bias_s[col + 1]);
      *reinterpret_cast<float2*>(&C[(size_t)row0 * G + bn + col]) =
          make_float2(acc[mi][ng][0] + bv.x, acc[mi][ng][1] + bv.y);
      *reinterpret_cast<float2*>(&C[(size_t)(row0 + 8) * G + bn + col]) =
          make_float2(acc[mi][ng][2] + bv.x, acc[mi][ng][3] + bv.y);
    }
  }
}

// ---------------------------------------------------------------------------
// Persistent BiLSTM recurrence with split-bf16 HMMA step GEMM.
// R15: redundant post-MMA sync removed (red is a dedicated smem region).
__global__ __launch_bounds__(256, 1)
void lstm_persistent(const float* __restrict__ pre_f,
                     const float* __restrict__ pre_b,
                     const __nv_bfloat16* __restrict__ whh_hi,
                     const __nv_bfloat16* __restrict__ whh_lo,
                     float* __restrict__ out_f32,
                     __nv_bfloat16* __restrict__ oahi,
                     __nv_bfloat16* __restrict__ oalo,
                     int write_f32) {
  constexpr int WSTR = 520;
  constexpr int ASTR = 264;
  constexpr unsigned W_LO = 33280;
  constexpr unsigned A_BASE = 66560;
  constexpr unsigned A_LOSZ = 33792;
  constexpr unsigned A_BUFSZ = 67584;
  constexpr unsigned PRE_OFF = 201728;
  constexpr unsigned RED_OFF = 209920;
  char* smem = dynsmem;
  const unsigned sb = s2u32(smem);
  float* pre_s = reinterpret_cast<float*>(smem + PRE_OFF);
  float4* red = reinterpret_cast<float4*>(smem + RED_OFF);

  const int dir = blockIdx.x >> 6;
  const int jt = blockIdx.x & 63;
  const int jblk = jt << 3;
  const int tid = threadIdx.x;
  const int lane = tid & 31;
  const int warp = tid >> 5;
  const int kh = warp >> 2;
  const int mw = warp & 3;
  const int wm = mw << 4;
  const int lrow16 = lane & 15;
  const int lcol8 = (lane >> 4) << 3;
  const float* pre = dir ? pre_b : pre_f;
  const __nv_bfloat16* whi = whh_hi + (size_t)dir * GH;
  const __nv_bfloat16* wlo = whh_lo + (size_t)dir * GH;

  for (int e = tid; e < 2048; e += 256) {
    int r = e >> 6;
    int c16 = e & 63;
    int g = r >> 3, jl = r & 7;
    size_t go = (size_t)(g * 512 + jblk + jl) * 512 + c16 * 8;
    unsigned so = (unsigned)(r * WSTR + c16 * 8) * 2;
    *reinterpret_cast<uint4*>(smem + so) =
        *reinterpret_cast<const uint4*>(whi + go);
    *reinterpret_cast<uint4*>(smem + W_LO + so) =
        *reinterpret_cast<const uint4*>(wlo + go);
  }

  float c_st[2][2];
  c_st[0][0] = c_st[0][1] = c_st[1][0] = c_st[1][1] = 0.f;

  const int er = lane >> 2;
  const int ec = (lane & 3) << 1;
  const int jg = jblk + ec;

  const int r0 = tid >> 2;
  const int c0 = tid & 3;
  auto load_chunk = [&](const __nv_bfloat16* hhi, const __nv_bfloat16* hlo,
                        int ch) {
    const int k0 = ch << 8;
    const unsigned base = sb + A_BASE + (unsigned)ch * A_BUFSZ;
#pragma unroll
    for (int e = 0; e < 8; e++) {
      int c16 = c0 + (e << 2);
      unsigned so = (unsigned)(r0 * ASTR + c16 * 8) * 2;
      size_t go = (size_t)r0 * 512 + k0 + c16 * 8;
      cp_async16(base + so, hhi + go);
      cp_async16(base + A_LOSZ + so, hlo + go);
    }
  };

  for (int t = 0; t < T; t++) {
    const int tt = dir ? (T - 1 - t) : t;
    const int par = t & 1;
    const __nv_bfloat16* hhi = g_hbf_hi[par][dir];
    const __nv_bfloat16* hlo = g_hbf_lo[par][dir];
    __nv_bfloat16* nhi = g_hbf_hi[par ^ 1][dir];
    __nv_bfloat16* nlo = g_hbf_lo[par ^ 1][dir];

    __syncthreads();
    load_chunk(hhi, hlo, 0);
    cp_commit();
    load_chunk(hhi, hlo, 1);
#pragma unroll
    for (int e = 0; e < 2; e++) {
      int cid = tid + (e << 8);
      int b = cid >> 3, seg = cid & 7;
      const float* src =
          pre + ((size_t)tt * 64 + b) * 2048 + (seg >> 1) * 512 + jblk +
          (seg & 1) * 4;
      cp_async16(sb + PRE_OFF + (unsigned)(b * 32 + seg * 4) * 4, src);
    }
    cp_commit();

    float acc[4][4];
#pragma unroll
    for (int g = 0; g < 4; g++)
#pragma unroll
      for (int q = 0; q < 4; q++) acc[g][q] = 0.f;

#pragma unroll
    for (int ch = 0; ch < 2; ch++) {
      if (ch == 0) cp_wait<1>(); else cp_wait<0>();
      __syncthreads();
      const unsigned abase = sb + A_BASE + (unsigned)ch * A_BUFSZ;
      const int kloc = kh << 7;
      const int kglob = (ch << 8) + kloc;
#pragma unroll
      for (int kk = 0; kk < 128; kk += 16) {
        unsigned ah[4], al[4], bh[2][4], bl[2][4];
        unsigned aoff =
            (unsigned)((wm + lrow16) * ASTR + kloc + kk + lcol8) * 2;
        ldmx4(ah, abase + aoff);
        ldmx4(al, abase + A_LOSZ + aoff);
#pragma unroll
        for (int ni = 0; ni < 2; ni++) {
          unsigned woff =
              (unsigned)((ni * 16 + lrow16) * WSTR + kglob + kk + lcol8) * 2;
          ldmx4(bh[ni], sb + woff);
          ldmx4(bl[ni], sb + W_LO + woff);
        }
#pragma unroll
        for (int g = 0; g < 4; g++) {
          unsigned h0 = bh[g >> 1][g & 1], h1 = bh[g >> 1][2 + (g & 1)];
          unsigned l0 = bl[g >> 1][g & 1], l1 = bl[g >> 1][2 + (g & 1)];
          hmma(acc[g], ah, h0, h1);
          hmma(acc[g], ah, l0, l1);
          hmma(acc[g], al, h0, h1);
        }
      }
    }

    // split-K reduce: red is a dedicated region, so only one sync needed
    // between the upper-half writes and lower-half reads.
    if (kh == 1) {
#pragma unroll
      for (int g = 0; g < 4; g++)
        red[(mw * 4 + g) * 32 + lane] =
            make_float4(acc[g][0], acc[g][1], acc[g][2], acc[g][3]);
    }
    __syncthreads();

    if (kh == 0) {
#pragma unroll
      for (int g = 0; g < 4; g++) {
        float4 r = red[(mw * 4 + g) * 32 + lane];
        acc[g][0] += r.x; acc[g][1] += r.y; acc[g][2] += r.z; acc[g][3] += r.w;
      }
#pragma unroll
      for (int i = 0; i < 2; i++) {
        int b = wm + er + i * 8;
        const float* pp = pre_s + b * 32 + ec;
        float2 pi = *reinterpret_cast<const float2*>(pp);
        float2 pf = *reinterpret_cast<const float2*>(pp + 8);
        float2 pg = *reinterpret_cast<const float2*>(pp + 16);
        float2 po = *reinterpret_cast<const float2*>(pp + 24);
        float gi0 = acc[0][i * 2] + pi.x, gi1 = acc[0][i * 2 + 1] + pi.y;
        float gf0 = acc[1][i * 2] + pf.x, gf1 = acc[1][i * 2 + 1] + pf.y;
        float gg0 = acc[2][i * 2] + pg.x, gg1 = acc[2][i * 2 + 1] + pg.y;
        float go0 = acc[3][i * 2] + po.x, go1 = acc[3][i * 2 + 1] + po.y;
        float c0 = sigf(gf0) * c_st[i][0] + sigf(gi0) * tanhf_fast(gg0);
        float c1 = sigf(gf1) * c_st[i][1] + sigf(gi1) * tanhf_fast(gg1);
        c_st[i][0] = c0; c_st[i][1] = c1;
        float h0 = sigf(go0) * tanhf_fast(c0);
        float h1 = sigf(go1) * tanhf_fast(c1);
        __nv_bfloat16 h0h = __float2bfloat16(h0);
        __nv_bfloat16 h1h = __float2bfloat16(h1);
        __nv_bfloat16 h0l = __float2bfloat16(h0 - __bfloat162float(h0h));
        __nv_bfloat16 h1l = __float2bfloat16(h1 - __bfloat162float(h1h));
        __nv_bfloat162 vh; vh.x = h0h; vh.y = h1h;
        __nv_bfloat162 vl; vl.x = h0l; vl.y = h1l;
        size_t orow = ((size_t)tt * 64 + b) * 1024 + dir * 512 + jg;
        if (write_f32) {
          *reinterpret_cast<float2*>(&out_f32[orow]) = make_float2(h0, h1);
        } else {
          *reinterpret_cast<__nv_bfloat162*>(&oahi[orow]) = vh;
          *reinterpret_cast<__nv_bfloat162*>(&oalo[orow]) = vl;
        }
        *reinterpret_cast<__nv_bfloat162*>(&nhi[b * 512 + jg]) = vh;
        *reinterpret_cast<__nv_bfloat162*>(&nlo[b * 512 + jg]) = vl;
      }
    }

    // distributed-flag grid barrier (per direction, 64 blocks), busy poll
    if (t != T - 1) {
      __threadfence();          // release: epilogue stores visible first
      __syncthreads();
      if (tid == 0) atomicExch(&g_arrive[dir][jt], (unsigned)(t + 1));
      if (tid < NBLK_PER_DIR) {
        volatile unsigned* fl = &g_arrive[dir][tid];
        while (*fl < (unsigned)(t + 1)) { }
      }
      __syncthreads();          // acquire via cp.async.cg (L2-coherent) reads
    }
  }
}

// ---------------------------------------------------------------------------
__global__ __launch_bounds__(256)
void fc_kernel(const float* __restrict__ inp,
               const float* __restrict__ Wt,
               const float* __restrict__ bias,
               float* __restrict__ out) {
  __shared__ float rs[8][1024];
  int r0 = blockIdx.x << 3;
#pragma unroll
  for (int l = threadIdx.x; l < 2048; l += 256) {
    int r = l >> 8, f4 = (l & 255) << 2;
    *reinterpret_cast<float4*>(&rs[r][f4]) =
        *reinterpret_cast<const float4*>(&inp[(size_t)(r0 + r) * 1024 + f4]);
  }
  __syncthreads();
  int r = threadIdx.x >> 5;
  int tg = threadIdx.x & 31;
  int tag2 = tg + 32;
  bool has2 = (tag2 < TAGS);
  float a0 = 0.f, a1 = 0.f;
  for (int k = 0; k < 1024; k += 4) {
    float4 xv = *reinterpret_cast<const float4*>(&rs[r][k]);
    float4 w0 = *reinterpret_cast<const float4*>(&Wt[(size_t)tg * 1024 + k]);
    a0 += xv.x * w0.x + xv.y * w0.y + xv.z * w0.z + xv.w * w0.w;
    if (has2) {
      float4 w1 = *reinterpret_cast<const float4*>(&Wt[(size_t)tag2 * 1024 + k]);
      a1 += xv.x * w1.x + xv.y * w1.y + xv.z * w1.z + xv.w * w1.w;
    }
  }
  int row = r0 + r;
  int tq = row >> 6, bb = row & 63;
  size_t obase = ((size_t)bb * T + tq) * TAGS;
  out[obase + tg] = a0 + bias[tg];
  if (has2) out[obase + tag2] = a1 + bias[tag2];
}

// ---------------------------------------------------------------------------
extern "C" void kernel_launch(void* const* d_in, const int* in_sizes, int n_in,
                              void* d_out, int out_size) {
  const int* x = (const int*)d_in[0];
  const float* emb = (const float*)d_in[2];
  const float* Wih_f1 = (const float*)d_in[3];
  const float* Whh_f1 = (const float*)d_in[4];
  const float* bih_f1 = (const float*)d_in[5];
  const float* bhh_f1 = (const float*)d_in[6];
  const float* Wih_b1 = (const float*)d_in[7];
  const float* Whh_b1 = (const float*)d_in[8];
  const float* bih_b1 = (const float*)d_in[9];
  const float* bhh_b1 = (const float*)d_in[10];
  const float* Wih_f2 = (const float*)d_in[11];
  const float* Whh_f2 = (const float*)d_in[12];
  const float* bih_f2 = (const float*)d_in[13];
  const float* bhh_f2 = (const float*)d_in[14];
  const float* Wih_b2 = (const float*)d_in[15];
  const float* Whh_b2 = (const float*)d_in[16];
  const float* bih_b2 = (const float*)d_in[17];
  const float* bhh_b2 = (const float*)d_in[18];
  const float* fcW = (const float*)d_in[19];
  const float* fcb = (const float*)d_in[20];
  float* out = (float*)d_out;

  float *pre_f, *pre_b, *out2;
  __nv_bfloat16 *ahi, *alo, *whi, *wlo, *whhhi, *whhlo;
  cudaGetSymbolAddress((void**)&pre_f, g_pre_f);
  cudaGetSymbolAddress((void**)&pre_b, g_pre_b);
  cudaGetSymbolAddress((void**)&out2, g_out2);
  cudaGetSymbolAddress((void**)&ahi, g_ahi);
  cudaGetSymbolAddress((void**)&alo, g_alo);
  cudaGetSymbolAddress((void**)&whi, g_whi);
  cudaGetSymbolAddress((void**)&wlo, g_wlo);
  cudaGetSymbolAddress((void**)&whhhi, g_whhhi);
  cudaGetSymbolAddress((void**)&whhlo, g_whhlo);

  constexpr int LSTM_SMEM = 209920 + 8192;           // 218,112 B
  constexpr int GEMM_SMEM = 4 * 2 * 128 * 40 * 2;    // 81,920 B (4 stages)
  static bool attr_set = false;
  if (!attr_set) {
    cudaFuncSetAttribute(lstm_persistent,
                         cudaFuncAttributeMaxDynamicSharedMemorySize, LSTM_SMEM);
    cudaFuncSetAttribute(gemm_split_kernel<512>,
                         cudaFuncAttributeMaxDynamicSharedMemorySize, GEMM_SMEM);
    cudaFuncSetAttribute(gemm_split_kernel<1024>,
                         cudaFuncAttributeMaxDynamicSharedMemorySize, GEMM_SMEM);
    attr_set = true;
  }

  dim3 gg(G / 128, M / 128);   // (16, 128)

  // Embedding + A split fused (stride 512)
  embed_split_kernel<<<M, 128>>>(x, emb, ahi, alo);

  // Layer 1 (K = 512)
  init_layer_kernel<<<(2 * 2 * B * H + 255) / 256, 256>>>();
  split_kernel<<<(G * E + 255) / 256, 256>>>(Wih_f1, whi, wlo, G * E);
  gemm_split_kernel<512><<<gg, 256, GEMM_SMEM>>>(ahi, alo, whi, wlo,
                                                 bih_f1, bhh_f1, pre_f);
  split_kernel<<<(G * E + 255) / 256, 256>>>(Wih_b1, whi, wlo, G * E);
  gemm_split_kernel<512><<<gg, 256, GEMM_SMEM>>>(ahi, alo, whi, wlo,
                                                 bih_b1, bhh_b1, pre_b);
  split_kernel<<<(GH + 255) / 256, 256>>>(Whh_f1, whhhi, whhlo, GH);
  split_kernel<<<(GH + 255) / 256, 256>>>(Whh_b1, whhhi + GH, whhlo + GH, GH);
  // Layer-1 recurrence: epilogue writes bf16 hi/lo layer-2 A rows (stride 1024)
  lstm_persistent<<<2 * NBLK_PER_DIR, 256, LSTM_SMEM>>>(
      pre_f, pre_b, whhhi, whhlo, out2, ahi, alo, 0);

  // Layer 2 (K = 1024)
  init_layer_kernel<<<(2 * 2 * B * H + 255) / 256, 256>>>();
  split_kernel<<<(G * 1024 + 255) / 256, 256>>>(Wih_f2, whi, wlo, G * 1024);
  gemm_split_kernel<1024><<<gg, 256, GEMM_SMEM>>>(ahi, alo, whi, wlo,
                                                  bih_f2, bhh_f2, pre_f);
  split_kernel<<<(G * 1024 + 255) / 256, 256>>>(Wih_b2, whi, wlo, G * 1024);
  gemm_split_kernel<1024><<<gg, 256, GEMM_SMEM>>>(ahi, alo, whi, wlo,
                                                  bih_b2, bhh_b2, pre_b);
  split_kernel<<<(GH + 255) / 256, 256>>>(Whh_f2, whhhi, whhlo, GH);
  split_kernel<<<(GH + 255) / 256, 256>>>(Whh_b2, whhhi + GH, whhlo + GH, GH);
  // Layer-2 recurrence: epilogue writes fp32 out2 for the FC head
  lstm_persistent<<<2 * NBLK_PER_DIR, 256, LSTM_SMEM>>>(
      pre_f, pre_b, whhhi, whhlo, out2, ahi, alo, 1);

  fc_kernel<<<M / 8, 256>>>(out2, fcW, fcb, out);
}

// round 16
// speedup vs baseline: 1.0244x; 1.0244x over previous
#include <cuda_runtime.h>
#include <cuda_bf16.h>
#include <math.h>

// Problem constants
namespace {
constexpr int B = 64, T = 256, E = 512, H = 512, TAGS = 50;
constexpr int G = 4 * H;   // 2048 (gate dim)
constexpr int M = T * B;   // 16384 rows
constexpr int NBLK_PER_DIR = 64;
constexpr int GH = G * H;  // 1M elements (one Whh)
}

// Single dynamic shared memory declaration for all kernels.
extern __shared__ char dynsmem[];

// Scratch (static device arrays — no cudaMalloc allowed)
__device__ float g_pre_f[M * G];
__device__ float g_pre_b[M * G];
__device__ float g_out2[M * 2 * H];
__device__ unsigned g_arrive[2][NBLK_PER_DIR];   // flag barrier slots
// bf16 split operands for tensor-core GEMMs
__device__ __align__(256) __nv_bfloat16 g_ahi[M * 1024];
__device__ __align__(256) __nv_bfloat16 g_alo[M * 1024];
__device__ __align__(256) __nv_bfloat16 g_whi[G * 1024];
__device__ __align__(256) __nv_bfloat16 g_wlo[G * 1024];
// recurrent weight splits (both dirs of current layer)
__device__ __align__(256) __nv_bfloat16 g_whhhi[2 * GH];
__device__ __align__(256) __nv_bfloat16 g_whhlo[2 * GH];
// h state in bf16 hi/lo, double buffered: [parity][dir][b*512 + j]
__device__ __align__(256) __nv_bfloat16 g_hbf_hi[2][2][B * H];
__device__ __align__(256) __nv_bfloat16 g_hbf_lo[2][2][B * H];

// ---------------------------------------------------------------------------
__device__ __forceinline__ unsigned s2u32(const void* p) {
  return static_cast<unsigned>(__cvta_generic_to_shared(p));
}
__device__ __forceinline__ void cp_async16(unsigned sa, const void* g) {
  asm volatile("cp.async.cg.shared.global [%0], [%1], 16;" :: "r"(sa), "l"(g));
}
__device__ __forceinline__ void cp_commit() {
  asm volatile("cp.async.commit_group;" ::: "memory");
}
template <int N>
__device__ __forceinline__ void cp_wait() {
  asm volatile("cp.async.wait_group %0;" :: "n"(N) : "memory");
}
__device__ __forceinline__ void ldmx4(unsigned* r, unsigned addr) {
  asm volatile("ldmatrix.sync.aligned.m8n8.x4.shared.b16 {%0,%1,%2,%3}, [%4];"
               : "=r"(r[0]), "=r"(r[1]), "=r"(r[2]), "=r"(r[3]) : "r"(addr));
}
__device__ __forceinline__ void hmma(float* d, const unsigned* a,
                                     unsigned b0, unsigned b1) {
  asm volatile(
      "mma.sync.aligned.m16n8k16.row.col.f32.bf16.bf16.f32 "
      "{%0,%1,%2,%3}, {%4,%5,%6,%7}, {%8,%9}, {%0,%1,%2,%3};"
      : "+f"(d[0]), "+f"(d[1]), "+f"(d[2]), "+f"(d[3])
      : "r"(a[0]), "r"(a[1]), "r"(a[2]), "r"(a[3]), "r"(b0), "r"(b1));
}
__device__ __forceinline__ float sigf(float x) {
  return __fdividef(1.f, 1.f + __expf(-x));
}
__device__ __forceinline__ float tanhf_fast(float x) {
  float e = __expf(2.f * x);
  return 1.f - __fdividef(2.f, e + 1.f);
}

// ---------------------------------------------------------------------------
__global__ void init_layer_kernel() {
  int i = blockIdx.x * blockDim.x + threadIdx.x;
  __nv_bfloat16* hh = &g_hbf_hi[0][0][0];
  __nv_bfloat16* hl = &g_hbf_lo[0][0][0];
  if (i < 2 * 2 * B * H) {
    hh[i] = __float2bfloat16(0.f);
    hl[i] = __float2bfloat16(0.f);
  }
  if (i < 2 * NBLK_PER_DIR) (&g_arrive[0][0])[i] = 0u;
}

// Embedding gather fused with bf16 hi/lo split: writes A operand directly.
__global__ void embed_split_kernel(const int* __restrict__ x,
                                   const float* __restrict__ emb,
                                   __nv_bfloat16* __restrict__ ahi,
                                   __nv_bfloat16* __restrict__ alo) {
  int row = blockIdx.x;
  int t = row >> 6;
  int b = row & 63;
  int tok = x[b * T + t];
  float4 v = reinterpret_cast<const float4*>(emb + (size_t)tok * E)[threadIdx.x];
  __nv_bfloat16 h0 = __float2bfloat16(v.x);
  __nv_bfloat16 h1 = __float2bfloat16(v.y);
  __nv_bfloat16 h2 = __float2bfloat16(v.z);
  __nv_bfloat16 h3 = __float2bfloat16(v.w);
  __nv_bfloat162 hi0; hi0.x = h0; hi0.y = h1;
  __nv_bfloat162 hi1; hi1.x = h2; hi1.y = h3;
  __nv_bfloat162 lo0, lo1;
  lo0.x = __float2bfloat16(v.x - __bfloat162float(h0));
  lo0.y = __float2bfloat16(v.y - __bfloat162float(h1));
  lo1.x = __float2bfloat16(v.z - __bfloat162float(h2));
  lo1.y = __float2bfloat16(v.w - __bfloat162float(h3));
  size_t o = (size_t)row * E + threadIdx.x * 4;
  *reinterpret_cast<__nv_bfloat162*>(ahi + o) = hi0;
  *reinterpret_cast<__nv_bfloat162*>(ahi + o + 2) = hi1;
  *reinterpret_cast<__nv_bfloat162*>(alo + o) = lo0;
  *reinterpret_cast<__nv_bfloat162*>(alo + o + 2) = lo1;
}

// fp32 -> (hi, lo) bf16 split (weights)
__global__ void split_kernel(const float* __restrict__ in,
                             __nv_bfloat16* __restrict__ hi,
                             __nv_bfloat16* __restrict__ lo, int n) {
  int i = blockIdx.x * blockDim.x + threadIdx.x;
  if (i < n) {
    float x = in[i];
    __nv_bfloat16 h = __float2bfloat16(x);
    hi[i] = h;
    lo[i] = __float2bfloat16(x - __bfloat162float(h));
  }
}

// ---------------------------------------------------------------------------
// Split-bf16 HMMA GEMM, R16: per 32-k chunk load ALL FOUR tiles
// (Ahi, Alo, Whi, Wlo) once and run all 3 products (Ah.Wh + Al.Wh + Ah.Wl)
// on them. 3x fewer chunks/syncs, 33% less smem-load traffic, ratio
// 12 LDSM : 48 HMMA per warp per kk. 2-stage double buffer, 2 CTAs/SM.
template <int K>
__global__ __launch_bounds__(256, 2)
void gemm_split_kernel(const __nv_bfloat16* __restrict__ Ahi,
                       const __nv_bfloat16* __restrict__ Alo,
                       const __nv_bfloat16* __restrict__ Whi,
                       const __nv_bfloat16* __restrict__ Wlo,
                       const float* __restrict__ b1,
                       const float* __restrict__ b2,
                       float* __restrict__ C) {
  constexpr int NCH = K / 32;
  constexpr int LDS_EL = 40;
  constexpr int TILE_EL = 128 * LDS_EL;          // 5120 el / tile
  constexpr unsigned TILE_B = TILE_EL * 2;       // 10240 B
  constexpr unsigned STAGE_B = 4 * TILE_B;       // 40960 B per stage
  __nv_bfloat16* smem = reinterpret_cast<__nv_bfloat16*>(dynsmem);
  __shared__ float bias_s[128];

  const int bn = blockIdx.x << 7;
  const int bm = blockIdx.y << 7;
  const int tid = threadIdx.x;
  const int lane = tid & 31;
  const int wid = tid >> 5;
  const int wm = (wid & 3) << 5;
  const int wn = (wid >> 2) << 6;

  if (tid < 128) bias_s[tid] = b1[bn + tid] + b2[bn + tid];

  const unsigned sb = s2u32(smem);

  // loader: 4 tiles x 128 rows x 4 c16-chunks = 2048 cp / 256 thr = 8 each
  const int lrow = tid >> 1;           // 0..127
  const int lc2 = (tid & 1) << 1;      // c16 base: 0 or 2
  auto load_chunk = [&](int ch) {
    const int k0 = ch << 5;
    const unsigned base = sb + (unsigned)(ch & 1) * STAGE_B;
#pragma unroll
    for (int e = 0; e < 2; e++) {
      int c16 = lc2 + e;
      unsigned so = (unsigned)(lrow * LDS_EL + c16 * 8) * 2;
      size_t goA = (size_t)(bm + lrow) * K + k0 + c16 * 8;
      size_t goW = (size_t)(bn + lrow) * K + k0 + c16 * 8;
      cp_async16(base + so, Ahi + goA);
      cp_async16(base + TILE_B + so, Alo + goA);
      cp_async16(base + 2 * TILE_B + so, Whi + goW);
      cp_async16(base + 3 * TILE_B + so, Wlo + goW);
    }
    cp_commit();
  };

  load_chunk(0);
  load_chunk(1);

  float acc[2][8][4];
#pragma unroll
  for (int mi = 0; mi < 2; mi++)
#pragma unroll
    for (int ng = 0; ng < 8; ng++)
#pragma unroll
      for (int q = 0; q < 4; q++) acc[mi][ng][q] = 0.f;

  const int lrow16 = lane & 15;
  const int lcol8 = (lane >> 4) << 3;
  const unsigned aoff0 = (unsigned)((wm + lrow16) * LDS_EL + lcol8) * 2;
  const unsigned aoff1 = (unsigned)((wm + 16 + lrow16) * LDS_EL + lcol8) * 2;
  unsigned woffs[4];
#pragma unroll
  for (int ni = 0; ni < 4; ni++)
    woffs[ni] =
        (unsigned)((wn + ni * 16 + lrow16) * LDS_EL + lcol8) * 2;

  for (int ch = 0; ch < NCH; ch++) {
    if (ch + 1 < NCH) cp_wait<1>(); else cp_wait<0>();
    __syncthreads();
    const unsigned base = sb + (unsigned)(ch & 1) * STAGE_B;
    const unsigned baseAl = base + TILE_B;
    const unsigned baseWh = base + 2 * TILE_B;
    const unsigned baseWl = base + 3 * TILE_B;
#pragma unroll
    for (int kk = 0; kk < 32; kk += 16) {
      unsigned ah[2][4], al[2][4], bh[4][4], bl[4][4];
      // product 1: Ah . Wh
      ldmx4(ah[0], base + aoff0 + kk * 2);
      ldmx4(ah[1], base + aoff1 + kk * 2);
#pragma unroll
      for (int ni = 0; ni < 4; ni++)
        ldmx4(bh[ni], baseWh + woffs[ni] + kk * 2);
#pragma unroll
      for (int mi = 0; mi < 2; mi++)
#pragma unroll
        for (int ng = 0; ng < 8; ng++)
          hmma(acc[mi][ng], ah[mi], bh[ng >> 1][ng & 1],
               bh[ng >> 1][2 + (ng & 1)]);
      // product 2: Al . Wh (bh still live, then dies)
      ldmx4(al[0], baseAl + aoff0 + kk * 2);
      ldmx4(al[1], baseAl + aoff1 + kk * 2);
#pragma unroll
      for (int mi = 0; mi < 2; mi++)
#pragma unroll
        for (int ng = 0; ng < 8; ng++)
          hmma(acc[mi][ng], al[mi], bh[ng >> 1][ng & 1],
               bh[ng >> 1][2 + (ng & 1)]);
      // product 3: Ah . Wl
#pragma unroll
      for (int ni = 0; ni < 4; ni++)
        ldmx4(bl[ni], baseWl + woffs[ni] + kk * 2);
#pragma unroll
      for (int mi = 0; mi < 2; mi++)
#pragma unroll
        for (int ng = 0; ng < 8; ng++)
          hmma(acc[mi][ng], ah[mi], bl[ng >> 1][ng & 1],
               bl[ng >> 1][2 + (ng & 1)]);
    }
    __syncthreads();
    if (ch + 2 < NCH) load_chunk(ch + 2);
  }

  const int er = lane >> 2;
  const int ec = (lane & 3) << 1;
#pragma unroll
  for (int mi = 0; mi < 2; mi++) {
    int row0 = bm + wm + mi * 16 + er;
#pragma unroll
    for (int ng = 0; ng < 8; ng++) {
      int col = wn + ng * 8 + ec;
      float2 bv = make_float2(bias_s[col], bias_s[col + 1]);
      *reinterpret_cast<float2*>(&C[(size_t)row0 * G + bn + col]) =
          make_float2(acc[mi][ng][0] + bv.x, acc[mi][ng][1] + bv.y);
      *reinterpret_cast<float2*>(&C[(size_t)(row0 + 8) * G + bn + col]) =
          make_float2(acc[mi][ng][2] + bv.x, acc[mi][ng][3] + bv.y);
    }
  }
}

// ---------------------------------------------------------------------------
// Persistent BiLSTM recurrence with split-bf16 HMMA step GEMM (R14-exact).
__global__ __launch_bounds__(256, 1)
void lstm_persistent(const float* __restrict__ pre_f,
                     const float* __restrict__ pre_b,
                     const __nv_bfloat16* __restrict__ whh_hi,
                     const __nv_bfloat16* __restrict__ whh_lo,
                     float* __restrict__ out_f32,
                     __nv_bfloat16* __restrict__ oahi,
                     __nv_bfloat16* __restrict__ oalo,
                     int write_f32) {
  constexpr int WSTR = 520;
  constexpr int ASTR = 264;
  constexpr unsigned W_LO = 33280;
  constexpr unsigned A_BASE = 66560;
  constexpr unsigned A_LOSZ = 33792;
  constexpr unsigned A_BUFSZ = 67584;
  constexpr unsigned PRE_OFF = 201728;
  constexpr unsigned RED_OFF = 209920;
  char* smem = dynsmem;
  const unsigned sb = s2u32(smem);
  float* pre_s = reinterpret_cast<float*>(smem + PRE_OFF);
  float4* red = reinterpret_cast<float4*>(smem + RED_OFF);

  const int dir = blockIdx.x >> 6;
  const int jt = blockIdx.x & 63;
  const int jblk = jt << 3;
  const int tid = threadIdx.x;
  const int lane = tid & 31;
  const int warp = tid >> 5;
  const int kh = warp >> 2;
  const int mw = warp & 3;
  const int wm = mw << 4;
  const int lrow16 = lane & 15;
  const int lcol8 = (lane >> 4) << 3;
  const float* pre = dir ? pre_b : pre_f;
  const __nv_bfloat16* whi = whh_hi + (size_t)dir * GH;
  const __nv_bfloat16* wlo = whh_lo + (size_t)dir * GH;

  for (int e = tid; e < 2048; e += 256) {
    int r = e >> 6;
    int c16 = e & 63;
    int g = r >> 3, jl = r & 7;
    size_t go = (size_t)(g * 512 + jblk + jl) * 512 + c16 * 8;
    unsigned so = (unsigned)(r * WSTR + c16 * 8) * 2;
    *reinterpret_cast<uint4*>(smem + so) =
        *reinterpret_cast<const uint4*>(whi + go);
    *reinterpret_cast<uint4*>(smem + W_LO + so) =
        *reinterpret_cast<const uint4*>(wlo + go);
  }

  float c_st[2][2];
  c_st[0][0] = c_st[0][1] = c_st[1][0] = c_st[1][1] = 0.f;

  const int er = lane >> 2;
  const int ec = (lane & 3) << 1;
  const int jg = jblk + ec;

  const int r0 = tid >> 2;
  const int c0 = tid & 3;
  auto load_chunk = [&](const __nv_bfloat16* hhi, const __nv_bfloat16* hlo,
                        int ch) {
    const int k0 = ch << 8;
    const unsigned base = sb + A_BASE + (unsigned)ch * A_BUFSZ;
#pragma unroll
    for (int e = 0; e < 8; e++) {
      int c16 = c0 + (e << 2);
      unsigned so = (unsigned)(r0 * ASTR + c16 * 8) * 2;
      size_t go = (size_t)r0 * 512 + k0 + c16 * 8;
      cp_async16(base + so, hhi + go);
      cp_async16(base + A_LOSZ + so, hlo + go);
    }
  };

  for (int t = 0; t < T; t++) {
    const int tt = dir ? (T - 1 - t) : t;
    const int par = t & 1;
    const __nv_bfloat16* hhi = g_hbf_hi[par][dir];
    const __nv_bfloat16* hlo = g_hbf_lo[par][dir];
    __nv_bfloat16* nhi = g_hbf_hi[par ^ 1][dir];
    __nv_bfloat16* nlo = g_hbf_lo[par ^ 1][dir];

    __syncthreads();
    load_chunk(hhi, hlo, 0);
    cp_commit();
    load_chunk(hhi, hlo, 1);
#pragma unroll
    for (int e = 0; e < 2; e++) {
      int cid = tid + (e << 8);
      int b = cid >> 3, seg = cid & 7;
      const float* src =
          pre + ((size_t)tt * 64 + b) * 2048 + (seg >> 1) * 512 + jblk +
          (seg & 1) * 4;
      cp_async16(sb + PRE_OFF + (unsigned)(b * 32 + seg * 4) * 4, src);
    }
    cp_commit();

    float acc[4][4];
#pragma unroll
    for (int g = 0; g < 4; g++)
#pragma unroll
      for (int q = 0; q < 4; q++) acc[g][q] = 0.f;

#pragma unroll
    for (int ch = 0; ch < 2; ch++) {
      if (ch == 0) cp_wait<1>(); else cp_wait<0>();
      __syncthreads();
      const unsigned abase = sb + A_BASE + (unsigned)ch * A_BUFSZ;
      const int kloc = kh << 7;
      const int kglob = (ch << 8) + kloc;
#pragma unroll
      for (int kk = 0; kk < 128; kk += 16) {
        unsigned ah[4], al[4], bh[2][4], bl[2][4];
        unsigned aoff =
            (unsigned)((wm + lrow16) * ASTR + kloc + kk + lcol8) * 2;
        ldmx4(ah, abase + aoff);
        ldmx4(al, abase + A_LOSZ + aoff);
#pragma unroll
        for (int ni = 0; ni < 2; ni++) {
          unsigned woff =
              (unsigned)((ni * 16 + lrow16) * WSTR + kglob + kk + lcol8) * 2;
          ldmx4(bh[ni], sb + woff);
          ldmx4(bl[ni], sb + W_LO + woff);
        }
#pragma unroll
        for (int g = 0; g < 4; g++) {
          unsigned h0 = bh[g >> 1][g & 1], h1 = bh[g >> 1][2 + (g & 1)];
          unsigned l0 = bl[g >> 1][g & 1], l1 = bl[g >> 1][2 + (g & 1)];
          hmma(acc[g], ah, h0, h1);
          hmma(acc[g], ah, l0, l1);
          hmma(acc[g], al, h0, h1);
        }
      }
    }

    __syncthreads();
    if (kh == 1) {
#pragma unroll
      for (int g = 0; g < 4; g++)
        red[(mw * 4 + g) * 32 + lane] =
            make_float4(acc[g][0], acc[g][1], acc[g][2], acc[g][3]);
    }
    __syncthreads();

    if (kh == 0) {
#pragma unroll
      for (int g = 0; g < 4; g++) {
        float4 r = red[(mw * 4 + g) * 32 + lane];
        acc[g][0] += r.x; acc[g][1] += r.y; acc[g][2] += r.z; acc[g][3] += r.w;
      }
#pragma unroll
      for (int i = 0; i < 2; i++) {
        int b = wm + er + i * 8;
        const float* pp = pre_s + b * 32 + ec;
        float2 pi = *reinterpret_cast<const float2*>(pp);
        float2 pf = *reinterpret_cast<const float2*>(pp + 8);
        float2 pg = *reinterpret_cast<const float2*>(pp + 16);
        float2 po = *reinterpret_cast<const float2*>(pp + 24);
        float gi0 = acc[0][i * 2] + pi.x, gi1 = acc[0][i * 2 + 1] + pi.y;
        float gf0 = acc[1][i * 2] + pf.x, gf1 = acc[1][i * 2 + 1] + pf.y;
        float gg0 = acc[2][i * 2] + pg.x, gg1 = acc[2][i * 2 + 1] + pg.y;
        float go0 = acc[3][i * 2] + po.x, go1 = acc[3][i * 2 + 1] + po.y;
        float c0 = sigf(gf0) * c_st[i][0] + sigf(gi0) * tanhf_fast(gg0);
        float c1 = sigf(gf1) * c_st[i][1] + sigf(gi1) * tanhf_fast(gg1);
        c_st[i][0] = c0; c_st[i][1] = c1;
        float h0 = sigf(go0) * tanhf_fast(c0);
        float h1 = sigf(go1) * tanhf_fast(c1);
        __nv_bfloat16 h0h = __float2bfloat16(h0);
        __nv_bfloat16 h1h = __float2bfloat16(h1);
        __nv_bfloat16 h0l = __float2bfloat16(h0 - __bfloat162float(h0h));
        __nv_bfloat16 h1l = __float2bfloat16(h1 - __bfloat162float(h1h));
        __nv_bfloat162 vh; vh.x = h0h; vh.y = h1h;
        __nv_bfloat162 vl; vl.x = h0l; vl.y = h1l;
        size_t orow = ((size_t)tt * 64 + b) * 1024 + dir * 512 + jg;
        if (write_f32) {
          *reinterpret_cast<float2*>(&out_f32[orow]) = make_float2(h0, h1);
        } else {
          *reinterpret_cast<__nv_bfloat162*>(&oahi[orow]) = vh;
          *reinterpret_cast<__nv_bfloat162*>(&oalo[orow]) = vl;
        }
        *reinterpret_cast<__nv_bfloat162*>(&nhi[b * 512 + jg]) = vh;
        *reinterpret_cast<__nv_bfloat162*>(&nlo[b * 512 + jg]) = vl;
      }
    }

    // distributed-flag grid barrier (per direction, 64 blocks), busy poll
    if (t != T - 1) {
      __threadfence();          // release: epilogue stores visible first
      __syncthreads();
      if (tid == 0) atomicExch(&g_arrive[dir][jt], (unsigned)(t + 1));
      if (tid < NBLK_PER_DIR) {
        volatile unsigned* fl = &g_arrive[dir][tid];
        while (*fl < (unsigned)(t + 1)) { }
      }
      __syncthreads();          // acquire via cp.async.cg (L2-coherent) reads
    }
  }
}

// ---------------------------------------------------------------------------
__global__ __launch_bounds__(256)
void fc_kernel(const float* __restrict__ inp,
               const float* __restrict__ Wt,
               const float* __restrict__ bias,
               float* __restrict__ out) {
  __shared__ float rs[8][1024];
  int r0 = blockIdx.x << 3;
#pragma unroll
  for (int l = threadIdx.x; l < 2048; l += 256) {
    int r = l >> 8, f4 = (l & 255) << 2;
    *reinterpret_cast<float4*>(&rs[r][f4]) =
        *reinterpret_cast<const float4*>(&inp[(size_t)(r0 + r) * 1024 + f4]);
  }
  __syncthreads();
  int r = threadIdx.x >> 5;
  int tg = threadIdx.x & 31;
  int tag2 = tg + 32;
  bool has2 = (tag2 < TAGS);
  float a0 = 0.f, a1 = 0.f;
  for (int k = 0; k < 1024; k += 4) {
    float4 xv = *reinterpret_cast<const float4*>(&rs[r][k]);
    float4 w0 = *reinterpret_cast<const float4*>(&Wt[(size_t)tg * 1024 + k]);
    a0 += xv.x * w0.x + xv.y * w0.y + xv.z * w0.z + xv.w * w0.w;
    if (has2) {
      float4 w1 = *reinterpret_cast<const float4*>(&Wt[(size_t)tag2 * 1024 + k]);
      a1 += xv.x * w1.x + xv.y * w1.y + xv.z * w1.z + xv.w * w1.w;
    }
  }
  int row = r0 + r;
  int tq = row >> 6, bb = row & 63;
  size_t obase = ((size_t)bb * T + tq) * TAGS;
  out[obase + tg] = a0 + bias[tg];
  if (has2) out[obase + tag2] = a1 + bias[tag2];
}

// ---------------------------------------------------------------------------
extern "C" void kernel_launch(void* const* d_in, const int* in_sizes, int n_in,
                              void* d_out, int out_size) {
  const int* x = (const int*)d_in[0];
  const float* emb = (const float*)d_in[2];
  const float* Wih_f1 = (const float*)d_in[3];
  const float* Whh_f1 = (const float*)d_in[4];
  const float* bih_f1 = (const float*)d_in[5];
  const float* bhh_f1 = (const float*)d_in[6];
  const float* Wih_b1 = (const float*)d_in[7];
  const float* Whh_b1 = (const float*)d_in[8];
  const float* bih_b1 = (const float*)d_in[9];
  const float* bhh_b1 = (const float*)d_in[10];
  const float* Wih_f2 = (const float*)d_in[11];
  const float* Whh_f2 = (const float*)d_in[12];
  const float* bih_f2 = (const float*)d_in[13];
  const float* bhh_f2 = (const float*)d_in[14];
  const float* Wih_b2 = (const float*)d_in[15];
  const float* Whh_b2 = (const float*)d_in[16];
  const float* bih_b2 = (const float*)d_in[17];
  const float* bhh_b2 = (const float*)d_in[18];
  const float* fcW = (const float*)d_in[19];
  const float* fcb = (const float*)d_in[20];
  float* out = (float*)d_out;

  float *pre_f, *pre_b, *out2;
  __nv_bfloat16 *ahi, *alo, *whi, *wlo, *whhhi, *whhlo;
  cudaGetSymbolAddress((void**)&pre_f, g_pre_f);
  cudaGetSymbolAddress((void**)&pre_b, g_pre_b);
  cudaGetSymbolAddress((void**)&out2, g_out2);
  cudaGetSymbolAddress((void**)&ahi, g_ahi);
  cudaGetSymbolAddress((void**)&alo, g_alo);
  cudaGetSymbolAddress((void**)&whi, g_whi);
  cudaGetSymbolAddress((void**)&wlo, g_wlo);
  cudaGetSymbolAddress((void**)&whhhi, g_whhhi);
  cudaGetSymbolAddress((void**)&whhlo, g_whhlo);

  constexpr int LSTM_SMEM = 209920 + 8192;           // 218,112 B
  constexpr int GEMM_SMEM = 2 * 4 * 128 * 40 * 2;    // 81,920 B (2 stages x 4 tiles)
  static bool attr_set = false;
  if (!attr_set) {
    cudaFuncSetAttribute(lstm_persistent,
                         cudaFuncAttributeMaxDynamicSharedMemorySize, LSTM_SMEM);
    cudaFuncSetAttribute(gemm_split_kernel<512>,
                         cudaFuncAttributeMaxDynamicSharedMemorySize, GEMM_SMEM);
    cudaFuncSetAttribute(gemm_split_kernel<1024>,
                         cudaFuncAttributeMaxDynamicSharedMemorySize, GEMM_SMEM);
    attr_set = true;
  }

  dim3 gg(G / 128, M / 128);   // (16, 128)

  // Embedding + A split fused (stride 512)
  embed_split_kernel<<<M, 128>>>(x, emb, ahi, alo);

  // Layer 1 (K = 512)
  init_layer_kernel<<<(2 * 2 * B * H + 255) / 256, 256>>>();
  split_kernel<<<(G * E + 255) / 256, 256>>>(Wih_f1, whi, wlo, G * E);
  gemm_split_kernel<512><<<gg, 256, GEMM_SMEM>>>(ahi, alo, whi, wlo,
                                                 bih_f1, bhh_f1, pre_f);
  split_kernel<<<(G * E + 255) / 256, 256>>>(Wih_b1, whi, wlo, G * E);
  gemm_split_kernel<512><<<gg, 256, GEMM_SMEM>>>(ahi, alo, whi, wlo,
                                                 bih_b1, bhh_b1, pre_b);
  split_kernel<<<(GH + 255) / 256, 256>>>(Whh_f1, whhhi, whhlo, GH);
  split_kernel<<<(GH + 255) / 256, 256>>>(Whh_b1, whhhi + GH, whhlo + GH, GH);
  // Layer-1 recurrence: epilogue writes bf16 hi/lo layer-2 A rows (stride 1024)
  lstm_persistent<<<2 * NBLK_PER_DIR, 256, LSTM_SMEM>>>(
      pre_f, pre_b, whhhi, whhlo, out2, ahi, alo, 0);

  // Layer 2 (K = 1024)
  init_layer_kernel<<<(2 * 2 * B * H + 255) / 256, 256>>>();
  split_kernel<<<(G * 1024 + 255) / 256, 256>>>(Wih_f2, whi, wlo, G * 1024);
  gemm_split_kernel<1024><<<gg, 256, GEMM_SMEM>>>(ahi, alo, whi, wlo,
                                                  bih_f2, bhh_f2, pre_f);
  split_kernel<<<(G * 1024 + 255) / 256, 256>>>(Wih_b2, whi, wlo, G * 1024);
  gemm_split_kernel<1024><<<gg, 256, GEMM_SMEM>>>(ahi, alo, whi, wlo,
                                                  bih_b2, bhh_b2, pre_b);
  split_kernel<<<(GH + 255) / 256, 256>>>(Whh_f2, whhhi, whhlo, GH);
  split_kernel<<<(GH + 255) / 256, 256>>>(Whh_b2, whhhi + GH, whhlo + GH, GH);
  // Layer-2 recurrence: epilogue writes fp32 out2 for the FC head
  lstm_persistent<<<2 * NBLK_PER_DIR, 256, LSTM_SMEM>>>(
      pre_f, pre_b, whhhi, whhlo, out2, ahi, alo, 1);

  fc_kernel<<<M / 8, 256>>>(out2, fcW, fcb, out);
}